// round 1
// baseline (speedup 1.0000x reference)
#include <cuda_runtime.h>

#define B_ 4
#define L_ 2048
#define D_ 512
#define H_ 8
#define E_ 64

// Scratch for projected Q/K/V in [B, H, L, E] layout (head-major so each
// (b,h) slice is a contiguous [L, E] matrix).
__device__ __align__(256) float g_q[B_ * H_ * L_ * E_];
__device__ __align__(256) float g_k[B_ * H_ * L_ * E_];
__device__ __align__(256) float g_v[B_ * H_ * L_ * E_];

// Tile config shared by all GEMM kernels: 64x64 CTA tile, BK=16, 256 threads,
// 4x4 register microtile per thread.
#define BM 64
#define BN 64
#define BK 16

// ---------------------------------------------------------------------------
// Kernel 1: QKV projection.  C = X @ W + bias, output scattered to [B,H,L,E].
// X: [B*L, D] row-major, W: [D, D] row-major, bias: [D].
// grid: (M/BM = 128, D/BN = 8, 3)   z selects q/k/v
// ---------------------------------------------------------------------------
__global__ void proj_kernel(const float* __restrict__ X0, const float* __restrict__ X1,
                            const float* __restrict__ X2,
                            const float* __restrict__ W0, const float* __restrict__ W1,
                            const float* __restrict__ W2,
                            const float* __restrict__ b0, const float* __restrict__ b1,
                            const float* __restrict__ b2)
{
    const float* X;
    const float* W;
    const float* bias;
    float* dst;
    int z = blockIdx.z;
    if (z == 0)      { X = X0; W = W0; bias = b0; dst = g_q; }
    else if (z == 1) { X = X1; W = W1; bias = b1; dst = g_k; }
    else             { X = X2; W = W2; bias = b2; dst = g_v; }

    __shared__ float As[BK][BM];
    __shared__ float Bs[BK][BN];

    int t  = threadIdx.x;
    int tx = t & 15;         // 0..15 -> N microtile
    int ty = t >> 4;         // 0..15 -> M microtile
    int m0 = blockIdx.x * BM;
    int n0 = blockIdx.y * BN;

    int ar = t >> 2;         // A tile row (0..63)
    int ac = (t & 3) * 4;    // A tile col (0,4,8,12)
    int br = t >> 4;         // B tile row (0..15)
    int bc = (t & 15) * 4;   // B tile col

    float acc[4][4] = {};

    for (int k0 = 0; k0 < D_; k0 += BK) {
        float4 av = *reinterpret_cast<const float4*>(X + (size_t)(m0 + ar) * D_ + k0 + ac);
        As[ac + 0][ar] = av.x;
        As[ac + 1][ar] = av.y;
        As[ac + 2][ar] = av.z;
        As[ac + 3][ar] = av.w;
        float4 bv = *reinterpret_cast<const float4*>(W + (size_t)(k0 + br) * D_ + n0 + bc);
        *reinterpret_cast<float4*>(&Bs[br][bc]) = bv;
        __syncthreads();
#pragma unroll
        for (int k = 0; k < BK; k++) {
            float4 a = *reinterpret_cast<const float4*>(&As[k][ty * 4]);
            float4 b = *reinterpret_cast<const float4*>(&Bs[k][tx * 4]);
            float aa[4] = {a.x, a.y, a.z, a.w};
            float bb[4] = {b.x, b.y, b.z, b.w};
#pragma unroll
            for (int i = 0; i < 4; i++)
#pragma unroll
                for (int j = 0; j < 4; j++) acc[i][j] += aa[i] * bb[j];
        }
        __syncthreads();
    }

#pragma unroll
    for (int i = 0; i < 4; i++) {
        int m  = m0 + ty * 4 + i;
        int bb = m >> 11;            // batch
        int l  = m & (L_ - 1);       // position
#pragma unroll
        for (int j = 0; j < 4; j++) {
            int n = n0 + tx * 4 + j;
            int h = n >> 6;
            int e = n & 63;
            dst[(((size_t)(bb * H_ + h)) * L_ + l) * E_ + e] = acc[i][j] + bias[n];
        }
    }
}

// ---------------------------------------------------------------------------
// Kernel 2: scores.  S[bh] = scale * Q[bh] @ K[bh]^T  -> written into attn area.
// Q,K: [L, E] row-major per (b,h).  grid: (L/BM=32, L/BN=32, B*H=32)
// ---------------------------------------------------------------------------
__global__ void scores_kernel(float* __restrict__ attn)
{
    int bh = blockIdx.z;
    const float* Q = g_q + (size_t)bh * L_ * E_;
    const float* K = g_k + (size_t)bh * L_ * E_;
    float* S = attn + (size_t)bh * L_ * L_;

    __shared__ float As[BK][BM];
    __shared__ float Bs[BK][BN];

    int t  = threadIdx.x;
    int tx = t & 15;
    int ty = t >> 4;
    int m0 = blockIdx.x * BM;
    int n0 = blockIdx.y * BN;

    int ar = t >> 2;
    int ac = (t & 3) * 4;

    float acc[4][4] = {};
    const float scale = 0.125f;   // 1/sqrt(64)

    for (int k0 = 0; k0 < E_; k0 += BK) {
        float4 av = *reinterpret_cast<const float4*>(Q + (size_t)(m0 + ar) * E_ + k0 + ac);
        As[ac + 0][ar] = av.x;
        As[ac + 1][ar] = av.y;
        As[ac + 2][ar] = av.z;
        As[ac + 3][ar] = av.w;
        float4 bv = *reinterpret_cast<const float4*>(K + (size_t)(n0 + ar) * E_ + k0 + ac);
        Bs[ac + 0][ar] = bv.x;
        Bs[ac + 1][ar] = bv.y;
        Bs[ac + 2][ar] = bv.z;
        Bs[ac + 3][ar] = bv.w;
        __syncthreads();
#pragma unroll
        for (int k = 0; k < BK; k++) {
            float4 a = *reinterpret_cast<const float4*>(&As[k][ty * 4]);
            float4 b = *reinterpret_cast<const float4*>(&Bs[k][tx * 4]);
            float aa[4] = {a.x, a.y, a.z, a.w};
            float bb[4] = {b.x, b.y, b.z, b.w};
#pragma unroll
            for (int i = 0; i < 4; i++)
#pragma unroll
                for (int j = 0; j < 4; j++) acc[i][j] += aa[i] * bb[j];
        }
        __syncthreads();
    }

#pragma unroll
    for (int i = 0; i < 4; i++) {
        int m = m0 + ty * 4 + i;
#pragma unroll
        for (int j = 0; j < 4; j++) {
            int n = n0 + tx * 4 + j;
            S[(size_t)m * L_ + n] = acc[i][j] * scale;
        }
    }
}

// ---------------------------------------------------------------------------
// Kernel 3: row softmax in place.  One CTA (256 threads) per row of 2048.
// grid: B*H*L = 65536
// ---------------------------------------------------------------------------
__global__ void softmax_kernel(float* __restrict__ attn)
{
    float* p = attn + (size_t)blockIdx.x * L_;
    int t    = threadIdx.x;
    int w    = t >> 5;
    int lane = t & 31;

    float4* pv = reinterpret_cast<float4*>(p);
    float4 a = pv[t];
    float4 b = pv[t + 256];

    float m = fmaxf(fmaxf(fmaxf(a.x, a.y), fmaxf(a.z, a.w)),
                    fmaxf(fmaxf(b.x, b.y), fmaxf(b.z, b.w)));
#pragma unroll
    for (int o = 16; o; o >>= 1) m = fmaxf(m, __shfl_xor_sync(0xffffffffu, m, o));

    __shared__ float smax[8];
    __shared__ float ssum[8];
    if (lane == 0) smax[w] = m;
    __syncthreads();
    m = smax[0];
#pragma unroll
    for (int i = 1; i < 8; i++) m = fmaxf(m, smax[i]);

    a.x = __expf(a.x - m); a.y = __expf(a.y - m);
    a.z = __expf(a.z - m); a.w = __expf(a.w - m);
    b.x = __expf(b.x - m); b.y = __expf(b.y - m);
    b.z = __expf(b.z - m); b.w = __expf(b.w - m);

    float s = a.x + a.y + a.z + a.w + b.x + b.y + b.z + b.w;
#pragma unroll
    for (int o = 16; o; o >>= 1) s += __shfl_xor_sync(0xffffffffu, s, o);
    if (lane == 0) ssum[w] = s;
    __syncthreads();
    s = ssum[0];
#pragma unroll
    for (int i = 1; i < 8; i++) s += ssum[i];

    float inv = 1.0f / s;
    a.x *= inv; a.y *= inv; a.z *= inv; a.w *= inv;
    b.x *= inv; b.y *= inv; b.z *= inv; b.w *= inv;
    pv[t] = a;
    pv[t + 256] = b;
}

// ---------------------------------------------------------------------------
// Kernel 4: out = attn @ V.   Per (b,h): [L,L] @ [L,E] -> [L,E], written into
// out[b, l, h*E + e].   grid: (L/BM = 32, 1, B*H = 32)
// ---------------------------------------------------------------------------
__global__ void av_kernel(const float* __restrict__ attn, float* __restrict__ out)
{
    int bh = blockIdx.z;
    int bb = bh >> 3;
    int h  = bh & 7;
    const float* A = attn + (size_t)bh * L_ * L_;
    const float* V = g_v + (size_t)bh * L_ * E_;

    __shared__ float As[BK][BM];
    __shared__ float Bs[BK][BN];

    int t  = threadIdx.x;
    int tx = t & 15;
    int ty = t >> 4;
    int m0 = blockIdx.x * BM;

    int ar = t >> 2;
    int ac = (t & 3) * 4;
    int br = t >> 4;
    int bc = (t & 15) * 4;

    float acc[4][4] = {};

    for (int k0 = 0; k0 < L_; k0 += BK) {
        float4 av = *reinterpret_cast<const float4*>(A + (size_t)(m0 + ar) * L_ + k0 + ac);
        As[ac + 0][ar] = av.x;
        As[ac + 1][ar] = av.y;
        As[ac + 2][ar] = av.z;
        As[ac + 3][ar] = av.w;
        float4 bv = *reinterpret_cast<const float4*>(V + (size_t)(k0 + br) * E_ + bc);
        *reinterpret_cast<float4*>(&Bs[br][bc]) = bv;
        __syncthreads();
#pragma unroll
        for (int k = 0; k < BK; k++) {
            float4 a = *reinterpret_cast<const float4*>(&As[k][ty * 4]);
            float4 b = *reinterpret_cast<const float4*>(&Bs[k][tx * 4]);
            float aa[4] = {a.x, a.y, a.z, a.w};
            float bb4[4] = {b.x, b.y, b.z, b.w};
#pragma unroll
            for (int i = 0; i < 4; i++)
#pragma unroll
                for (int j = 0; j < 4; j++) acc[i][j] += aa[i] * bb4[j];
        }
        __syncthreads();
    }

#pragma unroll
    for (int i = 0; i < 4; i++) {
        int l = m0 + ty * 4 + i;
#pragma unroll
        for (int j = 0; j < 4; j++) {
            int e = tx * 4 + j;
            out[((size_t)(bb * L_ + l)) * D_ + h * E_ + e] = acc[i][j];
        }
    }
}

// ---------------------------------------------------------------------------
extern "C" void kernel_launch(void* const* d_in, const int* in_sizes, int n_in,
                              void* d_out, int out_size)
{
    const float* queries = (const float*)d_in[0];
    const float* keys    = (const float*)d_in[1];
    const float* values  = (const float*)d_in[2];
    const float* Wq      = (const float*)d_in[3];
    const float* bq      = (const float*)d_in[4];
    const float* Wk      = (const float*)d_in[5];
    const float* bk      = (const float*)d_in[6];
    const float* Wv      = (const float*)d_in[7];
    const float* bv      = (const float*)d_in[8];

    float* out  = (float*)d_out;
    float* attn = out + (size_t)B_ * L_ * D_;   // tuple order: (out, attn)

    dim3 blk(256);
    proj_kernel<<<dim3((B_ * L_) / BM, D_ / BN, 3), blk>>>(
        queries, keys, values, Wq, Wk, Wv, bq, bk, bv);
    scores_kernel<<<dim3(L_ / BM, L_ / BN, B_ * H_), blk>>>(attn);
    softmax_kernel<<<dim3(B_ * H_ * L_), blk>>>(attn);
    av_kernel<<<dim3(L_ / BM, 1, B_ * H_), blk>>>(attn, out);
}

// round 3
// speedup vs baseline: 2.7312x; 2.7312x over previous
#include <cuda_runtime.h>
#include <cstdint>

#define B_ 4
#define L_ 2048
#define D_ 512
#define H_ 8
#define E_ 64

// Projected Q/K/V scratch, [B,H,L,E] (each (b,h) slice is contiguous [L,E]).
__device__ __align__(256) float g_q[B_ * H_ * L_ * E_];
__device__ __align__(256) float g_k[B_ * H_ * L_ * E_];
__device__ __align__(256) float g_v[B_ * H_ * L_ * E_];

// ---------------------------------------------------------------------------
// helpers
// ---------------------------------------------------------------------------
__device__ __forceinline__ uint32_t smem_u32(const void* p) {
    uint32_t a;
    asm("{ .reg .u64 t; cvta.to.shared.u64 t, %1; cvt.u32.u64 %0, t; }"
        : "=r"(a) : "l"(p));
    return a;
}

// D = A(16x8,row) * B(8x8,col) + D, tf32 inputs (raw f32 bits, HW truncates)
__device__ __forceinline__ void mma_tf32(float* d, const uint32_t* a, const uint32_t* b) {
    asm volatile(
        "mma.sync.aligned.m16n8k8.row.col.f32.tf32.tf32.f32 "
        "{%0,%1,%2,%3}, {%4,%5,%6,%7}, {%8,%9}, {%0,%1,%2,%3};"
        : "+f"(d[0]), "+f"(d[1]), "+f"(d[2]), "+f"(d[3])
        : "r"(a[0]), "r"(a[1]), "r"(a[2]), "r"(a[3]), "r"(b[0]), "r"(b[1]));
}

__device__ __forceinline__ void cp16(uint32_t dst, const void* src) {
    asm volatile("cp.async.cg.shared.global [%0], [%1], 16;"
                 :: "r"(dst), "l"(src) : "memory");
}
#define CP_COMMIT() asm volatile("cp.async.commit_group;" ::: "memory")
#define CP_WAIT(n)  asm volatile("cp.async.wait_group %0;" :: "n"(n) : "memory")

// ---------------------------------------------------------------------------
// Kernel 1: QKV projection via mma.sync.  C = X @ W + bias -> scatter [B,H,L,E].
// CTA 128x128, 8 warps (2M x 4N), K=512 in BK=32 chunks, cp.async double buffer.
// grid (64, 4, 3), 256 threads.
// SMEM: Xs[2][128][36], Ws[2][32][136]
// ---------------------------------------------------------------------------
static constexpr int PJ_XS = 128 * 36;          // floats per X buffer
static constexpr int PJ_WS = 32 * 136;          // floats per W buffer
static constexpr int PJ_SMEM = (2 * PJ_XS + 2 * PJ_WS) * 4;   // 71680 B

__global__ void __launch_bounds__(256) proj_mma(
    const float* __restrict__ X0, const float* __restrict__ X1, const float* __restrict__ X2,
    const float* __restrict__ W0, const float* __restrict__ W1, const float* __restrict__ W2,
    const float* __restrict__ b0, const float* __restrict__ b1, const float* __restrict__ b2)
{
    extern __shared__ float smf[];
    float* Xs = smf;
    float* Ws = smf + 2 * PJ_XS;
    uint32_t sX = smem_u32(Xs), sW = smem_u32(Ws);

    const float* X; const float* W; const float* bias; float* dst;
    int z = blockIdx.z;
    if (z == 0)      { X = X0; W = W0; bias = b0; dst = g_q; }
    else if (z == 1) { X = X1; W = W1; bias = b1; dst = g_k; }
    else             { X = X2; W = W2; bias = b2; dst = g_v; }

    int t = threadIdx.x;
    int lane = t & 31, wid = t >> 5;
    int gid = lane >> 2, tg = lane & 3;
    int warpM = wid >> 2, warpN = wid & 3;
    int m0 = blockIdx.x * 128, n0 = blockIdx.y * 128;

    float acc[4][4][4] = {};

    // stage loads for chunk kt into buffer buf
    auto stage = [&](int kt, int buf) {
        int k0 = kt * 32;
#pragma unroll
        for (int i = 0; i < 4; i++) {
            int idx = t + i * 256;            // 1024 float4: X 128x32
            int row = idx >> 3, cc = (idx & 7) * 4;
            cp16(sX + (buf * PJ_XS + row * 36 + cc) * 4,
                 X + (size_t)(m0 + row) * D_ + k0 + cc);
        }
#pragma unroll
        for (int i = 0; i < 4; i++) {
            int idx = t + i * 256;            // 1024 float4: W 32x128
            int row = idx >> 5, cc = (idx & 31) * 4;
            cp16(sW + (buf * PJ_WS + row * 136 + cc) * 4,
                 W + (size_t)(k0 + row) * D_ + n0 + cc);
        }
    };

    stage(0, 0); CP_COMMIT();
    const int NIT = D_ / 32;                 // 16
    for (int kt = 0; kt < NIT; kt++) {
        int p = kt & 1;
        if (kt + 1 < NIT) { stage(kt + 1, p ^ 1); CP_COMMIT(); CP_WAIT(1); }
        else              { CP_WAIT(0); }
        __syncthreads();

        const float* Ab = Xs + p * PJ_XS;
        const float* Bb = Ws + p * PJ_WS;
#pragma unroll
        for (int ks = 0; ks < 4; ks++) {
            int k0 = ks * 8;
            uint32_t a[4][4], b[4][2];
#pragma unroll
            for (int mt = 0; mt < 4; mt++) {
                const float* pa = Ab + (warpM * 64 + mt * 16 + gid) * 36 + k0 + tg;
                a[mt][0] = __float_as_uint(pa[0]);
                a[mt][1] = __float_as_uint(pa[8 * 36]);
                a[mt][2] = __float_as_uint(pa[4]);
                a[mt][3] = __float_as_uint(pa[8 * 36 + 4]);
            }
#pragma unroll
            for (int nt = 0; nt < 4; nt++) {
                const float* pb = Bb + (k0 + tg) * 136 + warpN * 32 + nt * 8 + gid;
                b[nt][0] = __float_as_uint(pb[0]);
                b[nt][1] = __float_as_uint(pb[4 * 136]);
            }
#pragma unroll
            for (int mt = 0; mt < 4; mt++)
#pragma unroll
                for (int nt = 0; nt < 4; nt++)
                    mma_tf32(acc[mt][nt], a[mt], b[nt]);
        }
        __syncthreads();
    }

    // epilogue: + bias, scatter to [B,H,L,E]
#pragma unroll
    for (int mt = 0; mt < 4; mt++) {
        int m = m0 + warpM * 64 + mt * 16 + gid;
        int bb = m >> 11;
        int l  = m & (L_ - 1);
#pragma unroll
        for (int nt = 0; nt < 4; nt++) {
            int n = n0 + warpN * 32 + nt * 8 + tg * 2;
            int h = n >> 6, e = n & 63;
            float2 bi = *reinterpret_cast<const float2*>(bias + n);
            float2 v0 = make_float2(acc[mt][nt][0] + bi.x, acc[mt][nt][1] + bi.y);
            float2 v1 = make_float2(acc[mt][nt][2] + bi.x, acc[mt][nt][3] + bi.y);
            *reinterpret_cast<float2*>(dst + (((size_t)(bb * H_ + h)) * L_ + l) * E_ + e) = v0;
            *reinterpret_cast<float2*>(dst + (((size_t)(bb * H_ + h)) * L_ + l + 8) * E_ + e) = v1;
        }
    }
}

// ---------------------------------------------------------------------------
// Kernel 2: scores via mma.sync.  S = scale * Q K^T per (b,h).
// CTA 128x128 output tile, full K=64 resident.  grid (16,16,32), 256 threads.
// SMEM: Qs[128][68], Ks[128][68]
// ---------------------------------------------------------------------------
static constexpr int S_SMEM = 2 * 128 * 68 * 4;   // 69632 B

__global__ void __launch_bounds__(256) scores_mma(float* __restrict__ attn)
{
    extern __shared__ float smf[];
    float* Qs = smf;
    float* Ks = smf + 128 * 68;

    int t = threadIdx.x;
    int lane = t & 31, wid = t >> 5;
    int gid = lane >> 2, tg = lane & 3;
    int warpM = wid >> 2, warpN = wid & 3;
    int m0 = blockIdx.x * 128, n0 = blockIdx.y * 128, bh = blockIdx.z;

    const float* Q = g_q + (size_t)bh * L_ * E_;
    const float* K = g_k + (size_t)bh * L_ * E_;
    float* S = attn + (size_t)bh * L_ * L_;

#pragma unroll
    for (int i = 0; i < 8; i++) {
        int idx = t + i * 256;               // 2048 float4 each
        int row = idx >> 4, cc = (idx & 15) * 4;
        *reinterpret_cast<float4*>(Qs + row * 68 + cc) =
            *reinterpret_cast<const float4*>(Q + (size_t)(m0 + row) * E_ + cc);
        *reinterpret_cast<float4*>(Ks + row * 68 + cc) =
            *reinterpret_cast<const float4*>(K + (size_t)(n0 + row) * E_ + cc);
    }
    __syncthreads();

    float acc[4][4][4] = {};
#pragma unroll
    for (int ks = 0; ks < 8; ks++) {
        int k0 = ks * 8;
        uint32_t a[4][4], b[4][2];
#pragma unroll
        for (int mt = 0; mt < 4; mt++) {
            const float* pa = Qs + (warpM * 64 + mt * 16 + gid) * 68 + k0 + tg;
            a[mt][0] = __float_as_uint(pa[0]);
            a[mt][1] = __float_as_uint(pa[8 * 68]);
            a[mt][2] = __float_as_uint(pa[4]);
            a[mt][3] = __float_as_uint(pa[8 * 68 + 4]);
        }
#pragma unroll
        for (int nt = 0; nt < 4; nt++) {
            const float* pb = Ks + (warpN * 32 + nt * 8 + gid) * 68 + k0 + tg;
            b[nt][0] = __float_as_uint(pb[0]);
            b[nt][1] = __float_as_uint(pb[4]);
        }
#pragma unroll
        for (int mt = 0; mt < 4; mt++)
#pragma unroll
            for (int nt = 0; nt < 4; nt++)
                mma_tf32(acc[mt][nt], a[mt], b[nt]);
    }

    const float scale = 0.125f;
#pragma unroll
    for (int mt = 0; mt < 4; mt++) {
        int r = m0 + warpM * 64 + mt * 16 + gid;
#pragma unroll
        for (int nt = 0; nt < 4; nt++) {
            int cc = n0 + warpN * 32 + nt * 8 + tg * 2;
            *reinterpret_cast<float2*>(S + (size_t)r * L_ + cc) =
                make_float2(acc[mt][nt][0] * scale, acc[mt][nt][1] * scale);
            *reinterpret_cast<float2*>(S + (size_t)(r + 8) * L_ + cc) =
                make_float2(acc[mt][nt][2] * scale, acc[mt][nt][3] * scale);
        }
    }
}

// ---------------------------------------------------------------------------
// Kernel 3: row softmax in place.  grid 65536, 256 threads.
// ---------------------------------------------------------------------------
__global__ void softmax_kernel(float* __restrict__ attn)
{
    float* p = attn + (size_t)blockIdx.x * L_;
    int t = threadIdx.x, w = t >> 5, lane = t & 31;

    float4* pv = reinterpret_cast<float4*>(p);
    float4 a = pv[t];
    float4 b = pv[t + 256];

    float m = fmaxf(fmaxf(fmaxf(a.x, a.y), fmaxf(a.z, a.w)),
                    fmaxf(fmaxf(b.x, b.y), fmaxf(b.z, b.w)));
#pragma unroll
    for (int o = 16; o; o >>= 1) m = fmaxf(m, __shfl_xor_sync(0xffffffffu, m, o));

    __shared__ float smax[8];
    __shared__ float ssum[8];
    if (lane == 0) smax[w] = m;
    __syncthreads();
    m = smax[0];
#pragma unroll
    for (int i = 1; i < 8; i++) m = fmaxf(m, smax[i]);

    a.x = __expf(a.x - m); a.y = __expf(a.y - m);
    a.z = __expf(a.z - m); a.w = __expf(a.w - m);
    b.x = __expf(b.x - m); b.y = __expf(b.y - m);
    b.z = __expf(b.z - m); b.w = __expf(b.w - m);

    float s = a.x + a.y + a.z + a.w + b.x + b.y + b.z + b.w;
#pragma unroll
    for (int o = 16; o; o >>= 1) s += __shfl_xor_sync(0xffffffffu, s, o);
    if (lane == 0) ssum[w] = s;
    __syncthreads();
    s = ssum[0];
#pragma unroll
    for (int i = 1; i < 8; i++) s += ssum[i];

    float inv = 1.0f / s;
    a.x *= inv; a.y *= inv; a.z *= inv; a.w *= inv;
    b.x *= inv; b.y *= inv; b.z *= inv; b.w *= inv;
    pv[t] = a;
    pv[t + 256] = b;
}

// ---------------------------------------------------------------------------
// Kernel 4: AV via mma.sync.  out = attn @ V per (b,h).
// CTA 128x64 output, K=2048 in BK=32 chunks, cp.async double buffer.
// 8 warps (4M x 2N).  grid (16,1,32), 256 threads.
// SMEM: As[2][128][36], Bs[2][32][72]
// ---------------------------------------------------------------------------
static constexpr int AV_AS = 128 * 36;
static constexpr int AV_BS = 32 * 72;
static constexpr int AV_SMEM = (2 * AV_AS + 2 * AV_BS) * 4;   // 55296 B

__global__ void __launch_bounds__(256) av_mma(const float* __restrict__ attn,
                                              float* __restrict__ out)
{
    extern __shared__ float smf[];
    float* As = smf;
    float* Bs = smf + 2 * AV_AS;
    uint32_t sA = smem_u32(As), sB = smem_u32(Bs);

    int t = threadIdx.x;
    int lane = t & 31, wid = t >> 5;
    int gid = lane >> 2, tg = lane & 3;
    int warpM = wid >> 1, warpN = wid & 1;
    int m0 = blockIdx.x * 128, bh = blockIdx.z;
    int bb = bh >> 3, h = bh & 7;

    const float* A = attn + (size_t)bh * L_ * L_;
    const float* V = g_v + (size_t)bh * L_ * E_;

    float acc[2][4][4] = {};

    auto stage = [&](int kt, int buf) {
        int k0 = kt * 32;
#pragma unroll
        for (int i = 0; i < 4; i++) {
            int idx = t + i * 256;            // 1024 float4: attn 128x32
            int row = idx >> 3, cc = (idx & 7) * 4;
            cp16(sA + (buf * AV_AS + row * 36 + cc) * 4,
                 A + (size_t)(m0 + row) * L_ + k0 + cc);
        }
#pragma unroll
        for (int i = 0; i < 2; i++) {
            int idx = t + i * 256;            // 512 float4: V 32x64
            int row = idx >> 4, cc = (idx & 15) * 4;
            cp16(sB + (buf * AV_BS + row * 72 + cc) * 4,
                 V + (size_t)(k0 + row) * E_ + cc);
        }
    };

    stage(0, 0); CP_COMMIT();
    const int NIT = L_ / 32;                  // 64
    for (int kt = 0; kt < NIT; kt++) {
        int p = kt & 1;
        if (kt + 1 < NIT) { stage(kt + 1, p ^ 1); CP_COMMIT(); CP_WAIT(1); }
        else              { CP_WAIT(0); }
        __syncthreads();

        const float* Ab = As + p * AV_AS;
        const float* Bb = Bs + p * AV_BS;
#pragma unroll
        for (int ks = 0; ks < 4; ks++) {
            int k0 = ks * 8;
            uint32_t a[2][4], b[4][2];
#pragma unroll
            for (int mt = 0; mt < 2; mt++) {
                const float* pa = Ab + (warpM * 32 + mt * 16 + gid) * 36 + k0 + tg;
                a[mt][0] = __float_as_uint(pa[0]);
                a[mt][1] = __float_as_uint(pa[8 * 36]);
                a[mt][2] = __float_as_uint(pa[4]);
                a[mt][3] = __float_as_uint(pa[8 * 36 + 4]);
            }
#pragma unroll
            for (int nt = 0; nt < 4; nt++) {
                const float* pb = Bb + (k0 + tg) * 72 + warpN * 32 + nt * 8 + gid;
                b[nt][0] = __float_as_uint(pb[0]);
                b[nt][1] = __float_as_uint(pb[4 * 72]);
            }
#pragma unroll
            for (int mt = 0; mt < 2; mt++)
#pragma unroll
                for (int nt = 0; nt < 4; nt++)
                    mma_tf32(acc[mt][nt], a[mt], b[nt]);
        }
        __syncthreads();
    }

#pragma unroll
    for (int mt = 0; mt < 2; mt++) {
        int r = m0 + warpM * 32 + mt * 16 + gid;
#pragma unroll
        for (int nt = 0; nt < 4; nt++) {
            int cc = warpN * 32 + nt * 8 + tg * 2;
            *reinterpret_cast<float2*>(out + ((size_t)(bb * L_ + r)) * D_ + h * 64 + cc) =
                make_float2(acc[mt][nt][0], acc[mt][nt][1]);
            *reinterpret_cast<float2*>(out + ((size_t)(bb * L_ + r + 8)) * D_ + h * 64 + cc) =
                make_float2(acc[mt][nt][2], acc[mt][nt][3]);
        }
    }
}

// ---------------------------------------------------------------------------
extern "C" void kernel_launch(void* const* d_in, const int* in_sizes, int n_in,
                              void* d_out, int out_size)
{
    const float* queries = (const float*)d_in[0];
    const float* keys    = (const float*)d_in[1];
    const float* values  = (const float*)d_in[2];
    const float* Wq      = (const float*)d_in[3];
    const float* bq      = (const float*)d_in[4];
    const float* Wk      = (const float*)d_in[5];
    const float* bk      = (const float*)d_in[6];
    const float* Wv      = (const float*)d_in[7];
    const float* bv      = (const float*)d_in[8];

    float* out  = (float*)d_out;
    float* attn = out + (size_t)B_ * L_ * D_;   // tuple order: (out, attn)

    static bool attr_set = false;
    if (!attr_set) {
        cudaFuncSetAttribute(proj_mma,   cudaFuncAttributeMaxDynamicSharedMemorySize, PJ_SMEM);
        cudaFuncSetAttribute(scores_mma, cudaFuncAttributeMaxDynamicSharedMemorySize, S_SMEM);
        cudaFuncSetAttribute(av_mma,     cudaFuncAttributeMaxDynamicSharedMemorySize, AV_SMEM);
        attr_set = true;
    }

    proj_mma<<<dim3((B_ * L_) / 128, D_ / 128, 3), 256, PJ_SMEM>>>(
        queries, keys, values, Wq, Wk, Wv, bq, bk, bv);
    scores_mma<<<dim3(L_ / 128, L_ / 128, B_ * H_), 256, S_SMEM>>>(attn);
    softmax_kernel<<<dim3(B_ * H_ * L_), 256>>>(attn);
    av_mma<<<dim3(L_ / 128, 1, B_ * H_), 256, AV_SMEM>>>(attn, out);
}